// round 5
// baseline (speedup 1.0000x reference)
#include <cuda_runtime.h>
#include <cstdint>

#define N_ATOMS 1024
#define NSHIFT 27
#define CUT2 25.0f                    // CUTOFF^2

#define ITILE 64                      // i-rows per block
#define JTILE 8                       // j-cols per block
#define BTHREADS 256
#define NWARPS 8
#define ROWS_PER_WARP (ITILE / NWARPS)   // 8 rows per warp
#define PAIRS_TILE (JTILE * NSHIFT)      // 216 pairs per row segment
#define ROW_FLOATS (PAIRS_TILE * 3)      // 648 floats
#define ROW_BYTES (ROW_FLOATS * 4)       // 2592 B (16B multiple)

// Scratch (static device globals — no allocation).
__device__ float4 g_B[N_ATOMS * NSHIFT];    // B[j][s] = cart[j] + shift_cart[s]
__device__ float4 g_cart[N_ATOMS];          // cart[i]

// Kernel 1: build cart + B table. Negligible time.
__global__ void build_B(const float* __restrict__ frac,
                        const float* __restrict__ cell) {
    int t = blockIdx.x * blockDim.x + threadIdx.x;
    if (t >= N_ATOMS * NSHIFT) return;
    int j = t / NSHIFT;
    int s = t - j * NSHIFT;

    float c[9];
#pragma unroll
    for (int m = 0; m < 9; m++) c[m] = __ldg(cell + m);

    float f0 = __ldg(frac + 3 * j + 0);
    float f1 = __ldg(frac + 3 * j + 1);
    float f2 = __ldg(frac + 3 * j + 2);

    float sx = (float)(s / 9 - 1);
    float sy = (float)((s / 3) % 3 - 1);
    float sz = (float)(s % 3 - 1);

    float cart[3], sc[3];
#pragma unroll
    for (int k = 0; k < 3; k++) {
        cart[k] = fmaf(f2, c[6 + k], fmaf(f1, c[3 + k], f0 * c[k]));
        sc[k]   = fmaf(sz, c[6 + k], fmaf(sy, c[3 + k], sx * c[k]));
    }

    g_B[t] = make_float4(__fadd_rn(cart[0], sc[0]),
                         __fadd_rn(cart[1], sc[1]),
                         __fadd_rn(cart[2], sc[2]), 0.0f);
    if (s == 0) g_cart[j] = make_float4(cart[0], cart[1], cart[2], 0.0f);
}

// Kernel 2: warp-private pipelines. Each warp owns rows {w, w+8, ...} of the
// block's 64-row tile, a private double-buffered SMEM row buffer, and its own
// per-thread bulk-group stream. No __syncthreads in the main loop.
__global__ void __launch_bounds__(BTHREADS)
radius_out(float* __restrict__ out) {
    __shared__ float4 shB[PAIRS_TILE];                           // 3456 B
    __shared__ __align__(16) float buf[NWARPS][2][ROW_FLOATS];   // 41472 B

    const int i0 = blockIdx.x * ITILE;
    const int j0 = blockIdx.y * JTILE;
    const int tid = threadIdx.x;
    const int w = tid >> 5;
    const int lane = tid & 31;

    for (int t = tid; t < PAIRS_TILE; t += BTHREADS)
        shB[t] = g_B[j0 * NSHIFT + t];
    __syncthreads();   // only barrier: shB visible to all warps

#pragma unroll 1
    for (int k = 0; k < ROWS_PER_WARP; k++) {
        float* bptr = buf[w][k & 1];
        const int i = i0 + w + NWARPS * k;

        // Buffer (k&1) was handed to a bulk group at iteration k-2; ensure that
        // group completed before overwriting. Per-warp slack = 2 iterations.
        if (k >= 2) {
            if (lane == 0)
                asm volatile("cp.async.bulk.wait_group 1;" ::: "memory");
            __syncwarp();
        }

        const float4 ci = __ldg(&g_cart[i]);   // L2-resident, once per row

        // Fill 216 pairs: conflict-free STS.32 (12B stride, gcd(3,32)=1).
#pragma unroll
        for (int p = lane; p < PAIRS_TILE; p += 32) {
            float4 bb = shB[p];
            float dx = __fadd_rn(bb.x, -ci.x);
            float dy = __fadd_rn(bb.y, -ci.y);
            float dz = __fadd_rn(bb.z, -ci.z);
            float d2 = __fadd_rn(__fadd_rn(__fmul_rn(dx, dx), __fmul_rn(dy, dy)),
                                 __fmul_rn(dz, dz));
            bool keep = d2 < CUT2;   // self-edge yields disp==+0 anyway
            int o = p * 3;
            bptr[o + 0] = keep ? dx : 0.0f;
            bptr[o + 1] = keep ? dy : 0.0f;
            bptr[o + 2] = keep ? dz : 0.0f;
        }
        __syncwarp();

        if (lane == 0) {
            asm volatile("fence.proxy.async.shared::cta;" ::: "memory");
            // contiguous row segment: out[(i*1024 + j0)*81 .. +648)
            float* gdst = out + (size_t)((size_t)i * N_ATOMS + (size_t)j0) * 81u;
            uint32_t ssrc = (uint32_t)__cvta_generic_to_shared(bptr);
            asm volatile(
                "cp.async.bulk.global.shared::cta.bulk_group [%0], [%1], %2;"
                :: "l"(gdst), "r"(ssrc), "r"((uint32_t)ROW_BYTES)
                : "memory");
            asm volatile("cp.async.bulk.commit_group;" ::: "memory");
        }
        __syncwarp();
    }

    // Drain this warp's outstanding bulk stores before exit.
    if (lane == 0)
        asm volatile("cp.async.bulk.wait_group 0;" ::: "memory");
}

extern "C" void kernel_launch(void* const* d_in, const int* in_sizes, int n_in,
                              void* d_out, int out_size) {
    const float* frac = (const float*)d_in[0];   // [1024,3]
    const float* cell = (const float*)d_in[1];   // [3,3]
    float* out = (float*)d_out;                  // [1024,1024,27,3]

    build_B<<<(N_ATOMS * NSHIFT + 255) / 256, 256>>>(frac, cell);
    dim3 grid(N_ATOMS / ITILE, N_ATOMS / JTILE); // (16, 128) = 2048 blocks
    radius_out<<<grid, BTHREADS>>>(out);
}

// round 6
// speedup vs baseline: 1.0709x; 1.0709x over previous
#include <cuda_runtime.h>
#include <cstdint>

#define N_ATOMS 1024
#define NSHIFT 27
#define CUT2 25.0f                      // CUTOFF^2

#define ITILE 8                         // i-rows per block
#define JTILE 64                        // j-atoms per block
#define BTHREADS 256
#define PAIRS_TILE (JTILE * NSHIFT)     // 1728 pairs per row segment
#define NP 7                            // ceil(1728/256) pairs per thread
#define SEG_FLOATS (PAIRS_TILE * 3)     // 5184 floats
#define SEG_BYTES (SEG_FLOATS * 4)      // 20736 B per TMA op (16B multiple)

// Single fused kernel: per-thread register-resident B vectors, SMEM staging,
// large double-buffered cp.async.bulk stores. No block-level B table, no LDS
// in the hot loop, one kernel launch total.
__global__ void __launch_bounds__(BTHREADS)
radius_out(const float* __restrict__ frac,
           const float* __restrict__ cell,
           float* __restrict__ out) {
    __shared__ __align__(16) float buf[2][SEG_FLOATS];   // 2 x 20736 B

    const int j0  = blockIdx.x * JTILE;    // x = j-segment: consecutive blocks
    const int i0  = blockIdx.y * ITILE;    //     write consecutive GMEM bands
    const int tid = threadIdx.x;

    float c[9];
#pragma unroll
    for (int m = 0; m < 9; m++) c[m] = __ldg(cell + m);

    // Per-thread B vectors: pairs p = tid + 256*k, k = 0..6 (k=6 partial).
    // B[p] = cart[j0 + p/27] + shift(p%27) @ cell, identical FP order to ref.
    float Bx[NP], By[NP], Bz[NP];
#pragma unroll
    for (int k = 0; k < NP; k++) {
        int p = tid + BTHREADS * k;
        if (p < PAIRS_TILE) {
            int j = p / NSHIFT;
            int s = p - NSHIFT * j;
            float f0 = __ldg(frac + 3 * (j0 + j) + 0);
            float f1 = __ldg(frac + 3 * (j0 + j) + 1);
            float f2 = __ldg(frac + 3 * (j0 + j) + 2);
            float sx = (float)(s / 9 - 1);
            float sy = (float)((s / 3) % 3 - 1);
            float sz = (float)(s % 3 - 1);
            float cj[3], sc[3];
#pragma unroll
            for (int q = 0; q < 3; q++) {
                cj[q] = fmaf(f2, c[6 + q], fmaf(f1, c[3 + q], f0 * c[q]));
                sc[q] = fmaf(sz, c[6 + q], fmaf(sy, c[3 + q], sx * c[q]));
            }
            Bx[k] = __fadd_rn(cj[0], sc[0]);
            By[k] = __fadd_rn(cj[1], sc[1]);
            Bz[k] = __fadd_rn(cj[2], sc[2]);
        }
    }

#pragma unroll 1
    for (int r = 0; r < ITILE; r++) {
        const int b = r & 1;
        const int i = i0 + r;

        // Buffer b was handed to a bulk group at iteration r-2; wait for that
        // group's SMEM read-out before overwriting.
        if (r >= 2) {
            if (tid == 0)
                asm volatile("cp.async.bulk.wait_group 1;" ::: "memory");
            __syncthreads();
        }

        // cart[i], same fmaf chain as reference (broadcast loads, L1-resident)
        float g0 = __ldg(frac + 3 * i + 0);
        float g1 = __ldg(frac + 3 * i + 1);
        float g2 = __ldg(frac + 3 * i + 2);
        float cix = fmaf(g2, c[6], fmaf(g1, c[3], g0 * c[0]));
        float ciy = fmaf(g2, c[7], fmaf(g1, c[4], g0 * c[1]));
        float ciz = fmaf(g2, c[8], fmaf(g1, c[5], g0 * c[2]));

        // Fill: conflict-free STS.32 (float stride 3 per lane, gcd(3,32)=1).
#pragma unroll
        for (int k = 0; k < NP; k++) {
            int p = tid + BTHREADS * k;
            if (p < PAIRS_TILE) {
                float dx = __fadd_rn(Bx[k], -cix);
                float dy = __fadd_rn(By[k], -ciy);
                float dz = __fadd_rn(Bz[k], -ciz);
                float d2 = __fadd_rn(__fadd_rn(__fmul_rn(dx, dx),
                                               __fmul_rn(dy, dy)),
                                     __fmul_rn(dz, dz));
                bool keep = d2 < CUT2;      // self-edge yields +0 anyway
                int o = p * 3;
                buf[b][o + 0] = keep ? dx : 0.0f;
                buf[b][o + 1] = keep ? dy : 0.0f;
                buf[b][o + 2] = keep ? dz : 0.0f;
            }
        }
        __syncthreads();

        if (tid == 0) {
            asm volatile("fence.proxy.async.shared::cta;" ::: "memory");
            // contiguous 20736B segment: out[(i*1024 + j0)*81 ...]
            float* gdst = out + (size_t)((size_t)i * N_ATOMS + (size_t)j0) * 81u;
            uint32_t ssrc = (uint32_t)__cvta_generic_to_shared(&buf[b][0]);
            asm volatile(
                "cp.async.bulk.global.shared::cta.bulk_group [%0], [%1], %2;"
                :: "l"(gdst), "r"(ssrc), "r"((uint32_t)SEG_BYTES)
                : "memory");
            asm volatile("cp.async.bulk.commit_group;" ::: "memory");
        }
    }

    // Drain all outstanding bulk stores before SMEM is released.
    if (tid == 0)
        asm volatile("cp.async.bulk.wait_group 0;" ::: "memory");
}

extern "C" void kernel_launch(void* const* d_in, const int* in_sizes, int n_in,
                              void* d_out, int out_size) {
    const float* frac = (const float*)d_in[0];   // [1024,3]
    const float* cell = (const float*)d_in[1];   // [3,3]
    float* out = (float*)d_out;                  // [1024,1024,27,3]

    dim3 grid(N_ATOMS / JTILE, N_ATOMS / ITILE); // (16, 128) = 2048 blocks
    radius_out<<<grid, BTHREADS>>>(frac, cell, out);
}